// round 15
// baseline (speedup 1.0000x reference)
#include <cuda_runtime.h>
#include <cuda_fp16.h>
#include <stdint.h>
#include <math.h>

#define NSAMP 64
#define NBLOCKS 5000           // 2 rays per block, M = 128 sample-rows
#define FXc 86.6f
#define NEAR_ 2.0f
#define FAR_ 6.0f
#define DINF 1e10f

// ---------------- global scratch (weights as fp16, [N][K]) ----------------
__device__ float g_z[NSAMP];
__device__ float g_dists[NSAMP];
__device__ float g_sig_last[10000];
__device__ __align__(16) __half g_w1T[256 * 64];
__device__ __align__(16) __half g_w2T[256 * 256];
__device__ __align__(16) __half g_wdT[128 * 256];

// ---------------- smem layout (bytes) ----------------
#define A_OFF     16384u
#define B_OFF     83968u
#define STAGE_B   36864u
#define BROW      144u
#define AROW      528u
#define SMEM_BYTES 194560

// misc float offsets
#define F_RAY   0      // [2][12]
#define F_B1    32
#define F_B2    288
#define F_WSIG  544
#define F_WRGB  800    // 384
#define F_EDIR  1184   // [2][32]
#define F_DC    1248   // [2][128]
#define F_SIGP  1504   // [4][128]
#define F_RGB   2016   // [128][3]
#define F_RGBP  2400   // [4][384]

// ---------------- asm helpers ----------------
__device__ __forceinline__ uint32_t smem_u32(const void* p) {
    uint32_t a;
    asm("{ .reg .u64 t; cvta.to.shared.u64 t, %1; cvt.u32.u64 %0, t; }" : "=r"(a) : "l"(p));
    return a;
}
__device__ __forceinline__ void sts32(uint32_t a, uint32_t v) {
    asm volatile("st.shared.b32 [%0], %1;" :: "r"(a), "r"(v));
}
__device__ __forceinline__ void ldsm4(uint32_t* r, uint32_t addr) {
    asm volatile("ldmatrix.sync.aligned.m8n8.x4.shared.b16 {%0,%1,%2,%3}, [%4];"
        : "=r"(r[0]), "=r"(r[1]), "=r"(r[2]), "=r"(r[3]) : "r"(addr));
}
__device__ __forceinline__ void mma_f16(float* c, const uint32_t* a, uint32_t b0, uint32_t b1) {
    asm volatile(
        "mma.sync.aligned.m16n8k16.row.col.f32.f16.f16.f32 "
        "{%0,%1,%2,%3}, {%4,%5,%6,%7}, {%8,%9}, {%0,%1,%2,%3};"
        : "+f"(c[0]), "+f"(c[1]), "+f"(c[2]), "+f"(c[3])
        : "r"(a[0]), "r"(a[1]), "r"(a[2]), "r"(a[3]), "r"(b0), "r"(b1));
}
__device__ __forceinline__ void cpa16(uint32_t d, const void* s) {
    asm volatile("cp.async.ca.shared.global [%0], [%1], 16;" :: "r"(d), "l"(s));
}
#define CP_COMMIT() asm volatile("cp.async.commit_group;" ::: "memory")
#define CP_WAIT1()  asm volatile("cp.async.wait_group 1;" ::: "memory")

__device__ __forceinline__ uint32_t pack_h2(float a, float b) {
    __half2 h = __floats2half2_rn(a, b);
    return *reinterpret_cast<uint32_t*>(&h);
}
__device__ __forceinline__ float qred(float v) {
    v += __shfl_xor_sync(0xffffffffu, v, 1);
    v += __shfl_xor_sync(0xffffffffu, v, 2);
    return v;
}

// schedule: 9 items = G1 x1, G2 x4, G3 x4 (K=64 chunks)
__device__ __forceinline__ void fill_item(int t, uint32_t bB, int tid) {
    if (t >= 9) return;
    const __half* src; int nrows, kst, kb;
    if (t == 0)      { src = g_w1T; nrows = 256; kst = 64;  kb = 0; }
    else if (t < 5)  { src = g_w2T; nrows = 256; kst = 256; kb = (t - 1) * 64; }
    else             { src = g_wdT; nrows = 128; kst = 256; kb = (t - 5) * 64; }
    uint32_t dst = bB + (uint32_t)(t % 3) * STAGE_B;
    for (int i = tid; i < nrows * 8; i += 512) {
        int n = i >> 3, seg = i & 7;
        cpa16(dst + (uint32_t)n * BROW + (uint32_t)seg * 16u,
              src + n * kst + kb + seg * 8);
    }
}

// GEMM: 4 M-warp-groups x 32 rows; 4 N-warp-groups. K=64/chunk, 3-stage ring,
// one barrier per chunk; next-next chunk's cp.async issued AFTER compute.
template<int NT>
__device__ __forceinline__ void gemm_run(float (*C)[4], int nchunks,
                                         uint32_t aP, uint32_t bB,
                                         int wn, int wm, int lane, int tid, int& t) {
    const uint32_t aBase = aP + (uint32_t)(wm * 32 + (lane & 15)) * AROW
                         + ((uint32_t)(lane >> 4) << 4);
    const uint32_t bOff = (uint32_t)(wn * (NT * 8) + (lane & 7) + ((lane >> 4) << 3)) * BROW
                        + (((uint32_t)(lane >> 3) & 1u) << 4);
    #pragma unroll
    for (int i = 0; i < 2 * NT; i++) { C[i][0] = 0.f; C[i][1] = 0.f; C[i][2] = 0.f; C[i][3] = 0.f; }
    #pragma unroll 1
    for (int ch = 0; ch < nchunks; ch++) {
        CP_WAIT1();
        __syncthreads();
        uint32_t bs = bB + (uint32_t)(t % 3) * STAGE_B + bOff;
        #pragma unroll
        for (int k16 = 0; k16 < 4; k16++) {
            uint32_t kb = (uint32_t)(ch * 128 + k16 * 32);
            uint32_t a0[4], a1[4];
            ldsm4(a0, aBase + kb);
            ldsm4(a1, aBase + 16u * AROW + kb);
            uint32_t b[NT / 2][4];
            #pragma unroll
            for (int p = 0; p < NT / 2; p++)
                ldsm4(b[p], bs + (uint32_t)p * 16u * BROW + (uint32_t)(k16 * 32));
            #pragma unroll
            for (int p = 0; p < NT / 2; p++) {
                mma_f16(C[2 * p],          a0, b[p][0], b[p][1]);
                mma_f16(C[2 * p + 1],      a0, b[p][2], b[p][3]);
                mma_f16(C[NT + 2 * p],     a1, b[p][0], b[p][1]);
                mma_f16(C[NT + 2 * p + 1], a1, b[p][2], b[p][3]);
            }
        }
        fill_item(t + 2, bB, tid);
        CP_COMMIT();
        t++;
    }
}

// ---------------- aux kernels ----------------
// block0 -> w1, block1 -> w2, block2 -> wd, block3 -> z/dists precompute
__global__ void prep_weights(const float* __restrict__ w1,
                             const float* __restrict__ w2,
                             const float* __restrict__ wd,
                             const float* __restrict__ t_rand) {
    int n = threadIdx.x;
    if (blockIdx.x == 0) {
        #pragma unroll 4
        for (int k = 0; k < 64; k++)
            g_w1T[n * 64 + k] = __float2half((k < 63) ? w1[k * 256 + n] : 0.0f);
    } else if (blockIdx.x == 1) {
        #pragma unroll 4
        for (int k = 0; k < 256; k++)
            g_w2T[n * 256 + k] = __float2half(w2[k * 256 + n]);
    } else if (blockIdx.x == 2) {
        if (n < 128) {
            #pragma unroll 4
            for (int k = 0; k < 256; k++)
                g_wdT[n * 256 + k] = __float2half(wd[k * 128 + n]);
        }
    } else {
        __shared__ float zsh[NSAMP];
        if (n < NSAMP) {
            int i = n;
            float t   = (float)i / 63.0f;
            float z0  = NEAR_ * (1.0f - t) + FAR_ * t;
            float tn  = (float)(i + 1) / 63.0f;
            float z0n = NEAR_ * (1.0f - tn) + FAR_ * tn;
            float tp  = (float)(i - 1) / 63.0f;
            float z0p = NEAR_ * (1.0f - tp) + FAR_ * tp;
            float upper = (i < NSAMP - 1) ? 0.5f * (z0 + z0n) : z0;
            float lower = (i > 0) ? 0.5f * (z0p + z0) : z0;
            float z = lower + (upper - lower) * t_rand[i];
            zsh[i] = z;
            g_z[i] = z;
        }
        __syncthreads();
        if (n < NSAMP)
            g_dists[n] = (n < NSAMP - 1) ? (zsh[n + 1] - zsh[n]) : DINF;
    }
}

// exact fp32 sigma for the LAST sample of each ray (alpha there is a step fn of
// sign(sigma)). 8 rays/block x 1250 blocks; z[63] inlined from t_rand.
__global__ void __launch_bounds__(256) sigma_exact(
    const float* __restrict__ c2w, const float* __restrict__ t_rand,
    const float* __restrict__ w1g, const float* __restrict__ b1g,
    const float* __restrict__ w2g, const float* __restrict__ b2g,
    const float* __restrict__ wsigg, const float* __restrict__ bsigg)
{
    __shared__ float enc[8][64];
    __shared__ float h1s[8][260];
    __shared__ float red[8][8];
    int tid = threadIdx.x;
    int r = tid >> 5, sub = tid & 31;
    {
        int ray = blockIdx.x * 8 + r;
        int cx = ray % 100, rw = ray / 100;
        float dx = ((float)cx - 50.0f) / FXc;
        float dy = -(((float)rw - 50.0f) / FXc);
        float d0 = dx * c2w[0] + dy * c2w[1] - c2w[2];
        float d1 = dx * c2w[4] + dy * c2w[5] - c2w[6];
        float d2 = dx * c2w[8] + dy * c2w[9] - c2w[10];
        // z[63]: upper = FAR, lower = mid(z0(62), FAR)
        float z062 = NEAR_ * (1.0f - 62.0f / 63.0f) + FAR_ * (62.0f / 63.0f);
        float lower = 0.5f * (z062 + FAR_);
        float z = lower + (FAR_ - lower) * t_rand[63];
        float pt[3];
        pt[0] = fmaf(d0, z, c2w[3]);
        pt[1] = fmaf(d1, z, c2w[7]);
        pt[2] = fmaf(d2, z, c2w[11]);
        #pragma unroll
        for (int q = 0; q < 2; q++) {
            int dd = sub * 2 + q;
            float val = 0.f;
            if (dd < 3) val = pt[dd];
            else if (dd < 63) {
                int u = dd - 3, l = u / 6, r6 = u % 6, cc = r6 % 3;
                float x = pt[cc] * (float)(1 << l);
                val = (r6 < 3) ? sinf(x) : cosf(x);
            }
            enc[r][dd] = val;
        }
    }
    __syncthreads();
    float acc[8];
    {
        float b = b1g[tid];
        #pragma unroll
        for (int i = 0; i < 8; i++) acc[i] = b;
        int k = 0;
        #pragma unroll 1
        for (; k + 3 < 63; k += 4) {
            float wa = w1g[k * 256 + tid];
            float wb = w1g[(k + 1) * 256 + tid];
            float wc = w1g[(k + 2) * 256 + tid];
            float wdv = w1g[(k + 3) * 256 + tid];
            #pragma unroll
            for (int i = 0; i < 8; i++)
                acc[i] = fmaf(enc[i][k], wa,
                         fmaf(enc[i][k + 1], wb,
                         fmaf(enc[i][k + 2], wc,
                         fmaf(enc[i][k + 3], wdv, acc[i]))));
        }
        #pragma unroll
        for (; k < 63; k++) {
            float w = w1g[k * 256 + tid];
            #pragma unroll
            for (int i = 0; i < 8; i++) acc[i] = fmaf(enc[i][k], w, acc[i]);
        }
        #pragma unroll
        for (int i = 0; i < 8; i++) h1s[i][tid] = fmaxf(acc[i], 0.f);
    }
    __syncthreads();
    {
        float b = b2g[tid];
        #pragma unroll
        for (int i = 0; i < 8; i++) acc[i] = b;
        #pragma unroll 1
        for (int k = 0; k < 256; k += 4) {
            float wa = w2g[k * 256 + tid];
            float wb = w2g[(k + 1) * 256 + tid];
            float wc = w2g[(k + 2) * 256 + tid];
            float wdv = w2g[(k + 3) * 256 + tid];
            #pragma unroll
            for (int i = 0; i < 8; i++)
                acc[i] = fmaf(h1s[i][k], wa,
                         fmaf(h1s[i][k + 1], wb,
                         fmaf(h1s[i][k + 2], wc,
                         fmaf(h1s[i][k + 3], wdv, acc[i]))));
        }
    }
    {
        float ws = wsigg[tid];
        #pragma unroll
        for (int i = 0; i < 8; i++) {
            float v = fmaxf(acc[i], 0.f) * ws;
            v += __shfl_xor_sync(0xffffffffu, v, 16);
            v += __shfl_xor_sync(0xffffffffu, v, 8);
            v += __shfl_xor_sync(0xffffffffu, v, 4);
            v += __shfl_xor_sync(0xffffffffu, v, 2);
            v += __shfl_xor_sync(0xffffffffu, v, 1);
            if ((tid & 31) == 0) red[i][tid >> 5] = v;
        }
        __syncthreads();
        if (tid < 8) {
            float s = bsigg[0];
            #pragma unroll
            for (int w = 0; w < 8; w++) s += red[tid][w];
            g_sig_last[blockIdx.x * 8 + tid] = s;
        }
    }
}

// ---------------- main fused kernel (512 threads) — unchanged from r14 ----------------
__global__ void __launch_bounds__(512, 1) nerf_v8(
    const float* __restrict__ c2w,
    const float* __restrict__ b1g,  const float* __restrict__ b2g,
    const float* __restrict__ wsigg,const float* __restrict__ bsigg,
    const float* __restrict__ wdirg,const float* __restrict__ bdirg,
    const float* __restrict__ wrgbg,const float* __restrict__ brgbg,
    float* __restrict__ out)
{
    extern __shared__ char smraw[];
    float* smf = (float*)smraw;
    const uint32_t base = smem_u32(smraw);
    const uint32_t aP = base + A_OFF, bB = base + B_OFF;
    const int tid = threadIdx.x, lane = tid & 31, wid = tid >> 5;
    const int wn = wid & 3, wm = wid >> 2;
    const int r0 = wm * 32 + (lane >> 2);
    const int ray0 = blockIdx.x * 2;
    int t = 0;

    fill_item(0, bB, tid); CP_COMMIT();
    fill_item(1, bB, tid); CP_COMMIT();

    if (tid < 256) {
        smf[F_B1 + tid]   = b1g[tid];
        smf[F_B2 + tid]   = b2g[tid];
        smf[F_WSIG + tid] = wsigg[tid];
    }
    if (tid < 384) smf[F_WRGB + tid] = wrgbg[tid];
    if (tid < 2) {
        int ray = ray0 + tid;
        int c = ray % 100, rw = ray / 100;
        float dx = ((float)c - 50.0f) / FXc;
        float dy = -(((float)rw - 50.0f) / FXc);
        float d0 = dx * c2w[0] + dy * c2w[1] - c2w[2];
        float d1 = dx * c2w[4] + dy * c2w[5] - c2w[6];
        float d2 = dx * c2w[8] + dy * c2w[9] - c2w[10];
        float nrm = sqrtf(d0 * d0 + d1 * d1 + d2 * d2);
        float* R = smf + F_RAY + tid * 12;
        R[0] = c2w[3]; R[1] = c2w[7]; R[2] = c2w[11];
        R[3] = d0; R[4] = d1; R[5] = d2;
        R[6] = d0 / nrm; R[7] = d1 / nrm; R[8] = d2 / nrm;
        R[9] = nrm;
    }
    __syncthreads();

    if (tid < 54) {
        int rr = tid / 27, dd = tid - rr * 27;
        const float* vv = smf + F_RAY + rr * 12 + 6;
        float val;
        if (dd < 3) val = vv[dd];
        else {
            int u = dd - 3, l = u / 6, r6 = u % 6, cc = r6 % 3;
            float x = vv[cc] * (float)(1 << l);
            val = (r6 < 3) ? sinf(x) : cosf(x);
        }
        smf[F_EDIR + rr * 32 + dd] = val;
    }
    __syncthreads();

    if (tid < 256) {
        int j = tid & 127, rr = tid >> 7;
        float acc = bdirg[j];
        #pragma unroll
        for (int dd = 0; dd < 27; dd++)
            acc = fmaf(smf[F_EDIR + rr * 32 + dd], wdirg[(256 + dd) * 128 + j], acc);
        smf[F_DC + rr * 128 + j] = acc;
    }

    if (tid < 128) {
        int rr = tid >> 6, s = tid & 63;
        float z = g_z[s];
        const float* R = smf + F_RAY + rr * 12;
        float v[64];
        float f0 = fmaf(R[3], z, R[0]);
        float f1 = fmaf(R[4], z, R[1]);
        float f2 = fmaf(R[5], z, R[2]);
        v[0] = f0; v[1] = f1; v[2] = f2;
        #pragma unroll
        for (int l = 0; l < 10; l++) {
            int b = 3 + l * 6;
            v[b]     = __sinf(f0); v[b + 1] = __sinf(f1); v[b + 2] = __sinf(f2);
            v[b + 3] = __cosf(f0); v[b + 4] = __cosf(f1); v[b + 5] = __cosf(f2);
            f0 *= 2.0f; f1 *= 2.0f; f2 *= 2.0f;
        }
        v[63] = 0.0f;
        uint32_t pk[32];
        #pragma unroll
        for (int i = 0; i < 32; i++) pk[i] = pack_h2(v[2 * i], v[2 * i + 1]);
        char* p = smraw + A_OFF + (uint32_t)tid * AROW;
        #pragma unroll
        for (int q = 0; q < 8; q++)
            *(uint4*)(p + q * 16) = ((uint4*)pk)[q];
    }

    float C[16][4];

    // ---------------- GEMM1: h1 = relu(enc @ w1 + b1), N=256, K=64 ----------------
    gemm_run<8>(C, 1, aP, bB, wn, wm, lane, tid, t);
    __syncthreads();
    {
        #pragma unroll
        for (int f = 0; f < 2; f++)
            #pragma unroll
            for (int nt = 0; nt < 8; nt++) {
                int col = wn * 64 + nt * 8 + 2 * (lane & 3);
                int row = r0 + f * 16;
                float2 bb = *(float2*)(smf + F_B1 + col);
                float* c = C[f * 8 + nt];
                float v0 = fmaxf(c[0] + bb.x, 0.f), v1 = fmaxf(c[1] + bb.y, 0.f);
                float v2 = fmaxf(c[2] + bb.x, 0.f), v3 = fmaxf(c[3] + bb.y, 0.f);
                uint32_t o0 = (uint32_t)row * AROW + (uint32_t)col * 2u;
                sts32(aP + o0, pack_h2(v0, v1));
                sts32(aP + o0 + 8 * AROW, pack_h2(v2, v3));
            }
    }

    // ---------------- GEMM2: h2 = relu(h1 @ w2 + b2), N=256, K=256 ----------------
    gemm_run<8>(C, 4, aP, bB, wn, wm, lane, tid, t);
    __syncthreads();
    {
        float sp[4] = {0.f, 0.f, 0.f, 0.f};
        #pragma unroll
        for (int f = 0; f < 2; f++)
            #pragma unroll
            for (int nt = 0; nt < 8; nt++) {
                int col = wn * 64 + nt * 8 + 2 * (lane & 3);
                int row = r0 + f * 16;
                float2 bb = *(float2*)(smf + F_B2 + col);
                float2 ws = *(float2*)(smf + F_WSIG + col);
                float* c = C[f * 8 + nt];
                float v0 = fmaxf(c[0] + bb.x, 0.f), v1 = fmaxf(c[1] + bb.y, 0.f);
                float v2 = fmaxf(c[2] + bb.x, 0.f), v3 = fmaxf(c[3] + bb.y, 0.f);
                sp[f * 2]     = fmaf(v0, ws.x, fmaf(v1, ws.y, sp[f * 2]));
                sp[f * 2 + 1] = fmaf(v2, ws.x, fmaf(v3, ws.y, sp[f * 2 + 1]));
                uint32_t o0 = (uint32_t)row * AROW + (uint32_t)col * 2u;
                sts32(aP + o0, pack_h2(v0, v1));
                sts32(aP + o0 + 8 * AROW, pack_h2(v2, v3));
            }
        #pragma unroll
        for (int q = 0; q < 4; q++) sp[q] = qred(sp[q]);
        if ((lane & 3) == 0) {
            float* P = smf + F_SIGP + wn * 128;
            P[r0]      = sp[0];
            P[r0 + 8]  = sp[1];
            P[r0 + 16] = sp[2];
            P[r0 + 24] = sp[3];
        }
    }

    // ---------------- GEMM3: hd = relu(h2 @ w_dir_top + dc), N=128, K=256 ----------
    gemm_run<4>(C, 4, aP, bB, wn, wm, lane, tid, t);
    __syncthreads();
    {
        int ray = wm >> 1;
        const float* dcp = smf + F_DC + ray * 128;
        float rp[4] = {0,0,0,0}, gp[4] = {0,0,0,0}, bp[4] = {0,0,0,0};
        #pragma unroll
        for (int f = 0; f < 2; f++)
            #pragma unroll
            for (int nt = 0; nt < 4; nt++) {
                int col = wn * 32 + nt * 8 + 2 * (lane & 3);
                float d0 = dcp[col], d1 = dcp[col + 1];
                float* c = C[f * 4 + nt];
                float h0 = fmaxf(c[0] + d0, 0.f), h1 = fmaxf(c[1] + d1, 0.f);
                float h2 = fmaxf(c[2] + d0, 0.f), h3 = fmaxf(c[3] + d1, 0.f);
                const float* w0 = smf + F_WRGB + col * 3;
                const float* w1v = w0 + 3;
                rp[f*2]   = fmaf(h0, w0[0], fmaf(h1, w1v[0], rp[f*2]));
                gp[f*2]   = fmaf(h0, w0[1], fmaf(h1, w1v[1], gp[f*2]));
                bp[f*2]   = fmaf(h0, w0[2], fmaf(h1, w1v[2], bp[f*2]));
                rp[f*2+1] = fmaf(h2, w0[0], fmaf(h3, w1v[0], rp[f*2+1]));
                gp[f*2+1] = fmaf(h2, w0[1], fmaf(h3, w1v[1], gp[f*2+1]));
                bp[f*2+1] = fmaf(h2, w0[2], fmaf(h3, w1v[2], bp[f*2+1]));
            }
        #pragma unroll
        for (int q = 0; q < 4; q++) { rp[q] = qred(rp[q]); gp[q] = qred(gp[q]); bp[q] = qred(bp[q]); }
        if ((lane & 3) == 0) {
            float* P = smf + F_RGBP + wn * 384;
            #pragma unroll
            for (int q = 0; q < 4; q++) {
                int row = r0 + q * 8;
                P[row * 3 + 0] = rp[q]; P[row * 3 + 1] = gp[q]; P[row * 3 + 2] = bp[q];
            }
        }
    }
    __syncthreads();

    if (tid < 128) {
        int row = tid, rr = row >> 6, s = row & 63;
        float sg = smf[F_SIGP + row] + smf[F_SIGP + 128 + row]
                 + smf[F_SIGP + 256 + row] + smf[F_SIGP + 384 + row] + bsigg[0];
        if (s == 63) sg = g_sig_last[ray0 + rr];
        float nrm = smf[F_RAY + rr * 12 + 9];
        smf[F_SIGP + row] = 1.0f - expf(-fmaxf(sg, 0.f) * g_dists[s] * nrm);
        #pragma unroll
        for (int c = 0; c < 3; c++) {
            float v = smf[F_RGBP + row * 3 + c] + smf[F_RGBP + 384 + row * 3 + c]
                    + smf[F_RGBP + 768 + row * 3 + c] + smf[F_RGBP + 1152 + row * 3 + c]
                    + brgbg[c];
            smf[F_RGB + row * 3 + c] = 1.0f / (1.0f + expf(-v));
        }
    }
    __syncthreads();

    if (tid < 2) {
        int ray = ray0 + tid;
        float T = 1.0f, r = 0.0f, g = 0.0f, b = 0.0f;
        #pragma unroll 1
        for (int s = 0; s < NSAMP; s++) {
            int m = tid * 64 + s;
            float a = smf[F_SIGP + m];
            float w = a * T;
            r = fmaf(w, smf[F_RGB + m * 3 + 0], r);
            g = fmaf(w, smf[F_RGB + m * 3 + 1], g);
            b = fmaf(w, smf[F_RGB + m * 3 + 2], b);
            T *= (1.0f - a);
        }
        out[ray * 3 + 0] = r;
        out[ray * 3 + 1] = g;
        out[ray * 3 + 2] = b;
    }
}

extern "C" void kernel_launch(void* const* d_in, const int* in_sizes, int n_in,
                              void* d_out, int out_size) {
    const float* c2w    = (const float*)d_in[0];
    const float* t_rand = (const float*)d_in[1];
    const float* w1     = (const float*)d_in[2];
    const float* b1     = (const float*)d_in[3];
    const float* w2     = (const float*)d_in[4];
    const float* b2     = (const float*)d_in[5];
    const float* w_sig  = (const float*)d_in[6];
    const float* b_sig  = (const float*)d_in[7];
    const float* w_dir  = (const float*)d_in[8];
    const float* b_dir  = (const float*)d_in[9];
    const float* w_rgb  = (const float*)d_in[10];
    const float* b_rgb  = (const float*)d_in[11];
    float* out = (float*)d_out;

    cudaFuncSetAttribute(nerf_v8, cudaFuncAttributeMaxDynamicSharedMemorySize, SMEM_BYTES);

    prep_weights<<<4, 256>>>(w1, w2, w_dir, t_rand);
    sigma_exact<<<1250, 256>>>(c2w, t_rand, w1, b1, w2, b2, w_sig, b_sig);
    nerf_v8<<<NBLOCKS, 512, SMEM_BYTES>>>(c2w, b1, b2, w_sig, b_sig,
                                          w_dir, b_dir, w_rgb, b_rgb, out);
}

// round 16
// speedup vs baseline: 1.0404x; 1.0404x over previous
#include <cuda_runtime.h>
#include <cuda_fp16.h>
#include <stdint.h>
#include <math.h>

#define NSAMP 64
#define NBLOCKS 5000           // 2 rays per block, M = 128 sample-rows
#define FXc 86.6f
#define NEAR_ 2.0f
#define FAR_ 6.0f
#define DINF 1e10f

// ---------------- global scratch (weights as fp16, [N][K]) ----------------
__device__ float g_z[NSAMP];
__device__ float g_dists[NSAMP];
__device__ float g_sig_last[10000];
__device__ __align__(16) __half g_w1T[256 * 64];
__device__ __align__(16) __half g_w2T[256 * 256];
__device__ __align__(16) __half g_wdT[128 * 256];

// ---------------- smem layout (bytes) ----------------
#define A_OFF     16384u
#define B_OFF     83968u
#define STAGE_B   36864u
#define BROW      144u
#define AROW      528u
#define SMEM_BYTES 194560

// misc float offsets
#define F_RAY   0      // [2][12]
#define F_B1    32
#define F_B2    288
#define F_WSIG  544
#define F_WRGB  800    // 384
#define F_EDIR  1184   // [2][32]
#define F_DC    1248   // [2][128]
#define F_SIGP  1504   // [4][128]
#define F_RGB   2016   // [128][3]
#define F_RGBP  2400   // [4][384]

// ---------------- asm helpers ----------------
__device__ __forceinline__ uint32_t smem_u32(const void* p) {
    uint32_t a;
    asm("{ .reg .u64 t; cvta.to.shared.u64 t, %1; cvt.u32.u64 %0, t; }" : "=r"(a) : "l"(p));
    return a;
}
__device__ __forceinline__ void sts32(uint32_t a, uint32_t v) {
    asm volatile("st.shared.b32 [%0], %1;" :: "r"(a), "r"(v));
}
__device__ __forceinline__ void ldsm4(uint32_t* r, uint32_t addr) {
    asm volatile("ldmatrix.sync.aligned.m8n8.x4.shared.b16 {%0,%1,%2,%3}, [%4];"
        : "=r"(r[0]), "=r"(r[1]), "=r"(r[2]), "=r"(r[3]) : "r"(addr));
}
__device__ __forceinline__ void mma_f16(float* c, const uint32_t* a, uint32_t b0, uint32_t b1) {
    asm volatile(
        "mma.sync.aligned.m16n8k16.row.col.f32.f16.f16.f32 "
        "{%0,%1,%2,%3}, {%4,%5,%6,%7}, {%8,%9}, {%0,%1,%2,%3};"
        : "+f"(c[0]), "+f"(c[1]), "+f"(c[2]), "+f"(c[3])
        : "r"(a[0]), "r"(a[1]), "r"(a[2]), "r"(a[3]), "r"(b0), "r"(b1));
}
__device__ __forceinline__ void cpa16(uint32_t d, const void* s) {
    asm volatile("cp.async.ca.shared.global [%0], [%1], 16;" :: "r"(d), "l"(s));
}
#define CP_COMMIT() asm volatile("cp.async.commit_group;" ::: "memory")
#define CP_WAIT1()  asm volatile("cp.async.wait_group 1;" ::: "memory")

__device__ __forceinline__ uint32_t pack_h2(float a, float b) {
    __half2 h = __floats2half2_rn(a, b);
    return *reinterpret_cast<uint32_t*>(&h);
}
__device__ __forceinline__ float qred(float v) {
    v += __shfl_xor_sync(0xffffffffu, v, 1);
    v += __shfl_xor_sync(0xffffffffu, v, 2);
    return v;
}

// schedule: 9 items = G1 x1, G2 x4, G3 x4 (K=64 chunks)
__device__ __forceinline__ void fill_item(int t, uint32_t bB, int tid) {
    if (t >= 9) return;
    const __half* src; int nrows, kst, kb;
    if (t == 0)      { src = g_w1T; nrows = 256; kst = 64;  kb = 0; }
    else if (t < 5)  { src = g_w2T; nrows = 256; kst = 256; kb = (t - 1) * 64; }
    else             { src = g_wdT; nrows = 128; kst = 256; kb = (t - 5) * 64; }
    uint32_t dst = bB + (uint32_t)(t % 3) * STAGE_B;
    for (int i = tid; i < nrows * 8; i += 512) {
        int n = i >> 3, seg = i & 7;
        cpa16(dst + (uint32_t)n * BROW + (uint32_t)seg * 16u,
              src + n * kst + kb + seg * 8);
    }
}

// GEMM: 4 M-warp-groups x 32 rows; 4 N-warp-groups. K=64/chunk, 3-stage ring,
// one barrier per chunk; next-next chunk's cp.async issued AFTER compute.
template<int NT>
__device__ __forceinline__ void gemm_run(float (*C)[4], int nchunks,
                                         uint32_t aP, uint32_t bB,
                                         int wn, int wm, int lane, int tid, int& t) {
    const uint32_t aBase = aP + (uint32_t)(wm * 32 + (lane & 15)) * AROW
                         + ((uint32_t)(lane >> 4) << 4);
    const uint32_t bOff = (uint32_t)(wn * (NT * 8) + (lane & 7) + ((lane >> 4) << 3)) * BROW
                        + (((uint32_t)(lane >> 3) & 1u) << 4);
    #pragma unroll
    for (int i = 0; i < 2 * NT; i++) { C[i][0] = 0.f; C[i][1] = 0.f; C[i][2] = 0.f; C[i][3] = 0.f; }
    #pragma unroll 1
    for (int ch = 0; ch < nchunks; ch++) {
        CP_WAIT1();
        __syncthreads();
        uint32_t bs = bB + (uint32_t)(t % 3) * STAGE_B + bOff;
        #pragma unroll
        for (int k16 = 0; k16 < 4; k16++) {
            uint32_t kb = (uint32_t)(ch * 128 + k16 * 32);
            uint32_t a0[4], a1[4];
            ldsm4(a0, aBase + kb);
            ldsm4(a1, aBase + 16u * AROW + kb);
            uint32_t b[NT / 2][4];
            #pragma unroll
            for (int p = 0; p < NT / 2; p++)
                ldsm4(b[p], bs + (uint32_t)p * 16u * BROW + (uint32_t)(k16 * 32));
            #pragma unroll
            for (int p = 0; p < NT / 2; p++) {
                mma_f16(C[2 * p],          a0, b[p][0], b[p][1]);
                mma_f16(C[2 * p + 1],      a0, b[p][2], b[p][3]);
                mma_f16(C[NT + 2 * p],     a1, b[p][0], b[p][1]);
                mma_f16(C[NT + 2 * p + 1], a1, b[p][2], b[p][3]);
            }
        }
        fill_item(t + 2, bB, tid);
        CP_COMMIT();
        t++;
    }
}

// ---------------- fused aux kernel ----------------
// blocks [0,448): weight transpose/convert, one element per thread (coalesced reads)
// blocks [448,1698): exact fp32 sigma for the LAST sample (8 rays/block)
// block 1698: z/dists precompute
#define PREP_BLOCKS 448
#define SIG_BLOCKS  1250
__global__ void __launch_bounds__(256) aux_kernel(
    const float* __restrict__ c2w, const float* __restrict__ t_rand,
    const float* __restrict__ w1g, const float* __restrict__ b1g,
    const float* __restrict__ w2g, const float* __restrict__ b2g,
    const float* __restrict__ wsigg, const float* __restrict__ bsigg,
    const float* __restrict__ wdg)
{
    __shared__ float enc[8][64];
    __shared__ float h1s[8][260];
    __shared__ float red[8][8];
    const int bid = blockIdx.x, tid = threadIdx.x;

    if (bid < PREP_BLOCKS) {
        // ---- weight prep: e = global element id; reads fully coalesced ----
        int e = bid * 256 + tid;
        if (e < 16384) {                    // w1T: n = e & 255, k = e >> 8 (0..63)
            int n = e & 255, k = e >> 8;
            g_w1T[n * 64 + k] = __float2half((k < 63) ? w1g[e] : 0.0f);
        } else if (e < 16384 + 65536) {     // w2T
            int u = e - 16384;
            int n = u & 255, k = u >> 8;
            g_w2T[n * 256 + k] = __float2half(w2g[u]);
        } else {                            // wdT
            int u = e - 16384 - 65536;
            int n = u & 127, k = u >> 7;
            g_wdT[n * 256 + k] = __float2half(wdg[u]);
        }
        return;
    }
    if (bid == PREP_BLOCKS + SIG_BLOCKS) {
        // ---- z / dists precompute ----
        if (tid < NSAMP) {
            int i = tid;
            float t   = (float)i / 63.0f;
            float z0  = NEAR_ * (1.0f - t) + FAR_ * t;
            float tn  = (float)(i + 1) / 63.0f;
            float z0n = NEAR_ * (1.0f - tn) + FAR_ * tn;
            float tp  = (float)(i - 1) / 63.0f;
            float z0p = NEAR_ * (1.0f - tp) + FAR_ * tp;
            float upper = (i < NSAMP - 1) ? 0.5f * (z0 + z0n) : z0;
            float lower = (i > 0) ? 0.5f * (z0p + z0) : z0;
            float z = lower + (upper - lower) * t_rand[i];
            enc[0][i] = z;                 // reuse shared as scratch
            g_z[i] = z;
        }
        __syncthreads();
        if (tid < NSAMP)
            g_dists[tid] = (tid < NSAMP - 1) ? (enc[0][tid + 1] - enc[0][tid]) : DINF;
        return;
    }

    // ---- sigma_exact: 8 rays/block; z[63] inlined from t_rand ----
    const int sb = bid - PREP_BLOCKS;
    int r = tid >> 5, sub = tid & 31;
    {
        int ray = sb * 8 + r;
        int cx = ray % 100, rw = ray / 100;
        float dx = ((float)cx - 50.0f) / FXc;
        float dy = -(((float)rw - 50.0f) / FXc);
        float d0 = dx * c2w[0] + dy * c2w[1] - c2w[2];
        float d1 = dx * c2w[4] + dy * c2w[5] - c2w[6];
        float d2 = dx * c2w[8] + dy * c2w[9] - c2w[10];
        float z062 = NEAR_ * (1.0f - 62.0f / 63.0f) + FAR_ * (62.0f / 63.0f);
        float lower = 0.5f * (z062 + FAR_);
        float z = lower + (FAR_ - lower) * t_rand[63];
        float pt[3];
        pt[0] = fmaf(d0, z, c2w[3]);
        pt[1] = fmaf(d1, z, c2w[7]);
        pt[2] = fmaf(d2, z, c2w[11]);
        #pragma unroll
        for (int q = 0; q < 2; q++) {
            int dd = sub * 2 + q;
            float val = 0.f;
            if (dd < 3) val = pt[dd];
            else if (dd < 63) {
                int u = dd - 3, l = u / 6, r6 = u % 6, cc = r6 % 3;
                float x = pt[cc] * (float)(1 << l);
                val = (r6 < 3) ? sinf(x) : cosf(x);
            }
            enc[r][dd] = val;
        }
    }
    __syncthreads();
    float acc[8];
    {
        float b = b1g[tid];
        #pragma unroll
        for (int i = 0; i < 8; i++) acc[i] = b;
        int k = 0;
        #pragma unroll 1
        for (; k + 3 < 63; k += 4) {
            float wa = w1g[k * 256 + tid];
            float wb = w1g[(k + 1) * 256 + tid];
            float wc = w1g[(k + 2) * 256 + tid];
            float wdv = w1g[(k + 3) * 256 + tid];
            #pragma unroll
            for (int i = 0; i < 8; i++)
                acc[i] = fmaf(enc[i][k], wa,
                         fmaf(enc[i][k + 1], wb,
                         fmaf(enc[i][k + 2], wc,
                         fmaf(enc[i][k + 3], wdv, acc[i]))));
        }
        #pragma unroll
        for (; k < 63; k++) {
            float w = w1g[k * 256 + tid];
            #pragma unroll
            for (int i = 0; i < 8; i++) acc[i] = fmaf(enc[i][k], w, acc[i]);
        }
        #pragma unroll
        for (int i = 0; i < 8; i++) h1s[i][tid] = fmaxf(acc[i], 0.f);
    }
    __syncthreads();
    {
        float b = b2g[tid];
        #pragma unroll
        for (int i = 0; i < 8; i++) acc[i] = b;
        #pragma unroll 1
        for (int k = 0; k < 256; k += 4) {
            float wa = w2g[k * 256 + tid];
            float wb = w2g[(k + 1) * 256 + tid];
            float wc = w2g[(k + 2) * 256 + tid];
            float wdv = w2g[(k + 3) * 256 + tid];
            #pragma unroll
            for (int i = 0; i < 8; i++)
                acc[i] = fmaf(h1s[i][k], wa,
                         fmaf(h1s[i][k + 1], wb,
                         fmaf(h1s[i][k + 2], wc,
                         fmaf(h1s[i][k + 3], wdv, acc[i]))));
        }
    }
    {
        float ws = wsigg[tid];
        #pragma unroll
        for (int i = 0; i < 8; i++) {
            float v = fmaxf(acc[i], 0.f) * ws;
            v += __shfl_xor_sync(0xffffffffu, v, 16);
            v += __shfl_xor_sync(0xffffffffu, v, 8);
            v += __shfl_xor_sync(0xffffffffu, v, 4);
            v += __shfl_xor_sync(0xffffffffu, v, 2);
            v += __shfl_xor_sync(0xffffffffu, v, 1);
            if ((tid & 31) == 0) red[i][tid >> 5] = v;
        }
        __syncthreads();
        if (tid < 8) {
            float s = bsigg[0];
            #pragma unroll
            for (int w = 0; w < 8; w++) s += red[tid][w];
            g_sig_last[sb * 8 + tid] = s;
        }
    }
}

// ---------------- main fused kernel (512 threads) — unchanged from r14 ----------------
__global__ void __launch_bounds__(512, 1) nerf_v9(
    const float* __restrict__ c2w,
    const float* __restrict__ b1g,  const float* __restrict__ b2g,
    const float* __restrict__ wsigg,const float* __restrict__ bsigg,
    const float* __restrict__ wdirg,const float* __restrict__ bdirg,
    const float* __restrict__ wrgbg,const float* __restrict__ brgbg,
    float* __restrict__ out)
{
    extern __shared__ char smraw[];
    float* smf = (float*)smraw;
    const uint32_t base = smem_u32(smraw);
    const uint32_t aP = base + A_OFF, bB = base + B_OFF;
    const int tid = threadIdx.x, lane = tid & 31, wid = tid >> 5;
    const int wn = wid & 3, wm = wid >> 2;
    const int r0 = wm * 32 + (lane >> 2);
    const int ray0 = blockIdx.x * 2;
    int t = 0;

    fill_item(0, bB, tid); CP_COMMIT();
    fill_item(1, bB, tid); CP_COMMIT();

    if (tid < 256) {
        smf[F_B1 + tid]   = b1g[tid];
        smf[F_B2 + tid]   = b2g[tid];
        smf[F_WSIG + tid] = wsigg[tid];
    }
    if (tid < 384) smf[F_WRGB + tid] = wrgbg[tid];
    if (tid < 2) {
        int ray = ray0 + tid;
        int c = ray % 100, rw = ray / 100;
        float dx = ((float)c - 50.0f) / FXc;
        float dy = -(((float)rw - 50.0f) / FXc);
        float d0 = dx * c2w[0] + dy * c2w[1] - c2w[2];
        float d1 = dx * c2w[4] + dy * c2w[5] - c2w[6];
        float d2 = dx * c2w[8] + dy * c2w[9] - c2w[10];
        float nrm = sqrtf(d0 * d0 + d1 * d1 + d2 * d2);
        float* R = smf + F_RAY + tid * 12;
        R[0] = c2w[3]; R[1] = c2w[7]; R[2] = c2w[11];
        R[3] = d0; R[4] = d1; R[5] = d2;
        R[6] = d0 / nrm; R[7] = d1 / nrm; R[8] = d2 / nrm;
        R[9] = nrm;
    }
    __syncthreads();

    if (tid < 54) {
        int rr = tid / 27, dd = tid - rr * 27;
        const float* vv = smf + F_RAY + rr * 12 + 6;
        float val;
        if (dd < 3) val = vv[dd];
        else {
            int u = dd - 3, l = u / 6, r6 = u % 6, cc = r6 % 3;
            float x = vv[cc] * (float)(1 << l);
            val = (r6 < 3) ? sinf(x) : cosf(x);
        }
        smf[F_EDIR + rr * 32 + dd] = val;
    }
    __syncthreads();

    if (tid < 256) {
        int j = tid & 127, rr = tid >> 7;
        float acc = bdirg[j];
        #pragma unroll
        for (int dd = 0; dd < 27; dd++)
            acc = fmaf(smf[F_EDIR + rr * 32 + dd], wdirg[(256 + dd) * 128 + j], acc);
        smf[F_DC + rr * 128 + j] = acc;
    }

    if (tid < 128) {
        int rr = tid >> 6, s = tid & 63;
        float z = g_z[s];
        const float* R = smf + F_RAY + rr * 12;
        float v[64];
        float f0 = fmaf(R[3], z, R[0]);
        float f1 = fmaf(R[4], z, R[1]);
        float f2 = fmaf(R[5], z, R[2]);
        v[0] = f0; v[1] = f1; v[2] = f2;
        #pragma unroll
        for (int l = 0; l < 10; l++) {
            int b = 3 + l * 6;
            v[b]     = __sinf(f0); v[b + 1] = __sinf(f1); v[b + 2] = __sinf(f2);
            v[b + 3] = __cosf(f0); v[b + 4] = __cosf(f1); v[b + 5] = __cosf(f2);
            f0 *= 2.0f; f1 *= 2.0f; f2 *= 2.0f;
        }
        v[63] = 0.0f;
        uint32_t pk[32];
        #pragma unroll
        for (int i = 0; i < 32; i++) pk[i] = pack_h2(v[2 * i], v[2 * i + 1]);
        char* p = smraw + A_OFF + (uint32_t)tid * AROW;
        #pragma unroll
        for (int q = 0; q < 8; q++)
            *(uint4*)(p + q * 16) = ((uint4*)pk)[q];
    }

    float C[16][4];

    // ---------------- GEMM1: h1 = relu(enc @ w1 + b1), N=256, K=64 ----------------
    gemm_run<8>(C, 1, aP, bB, wn, wm, lane, tid, t);
    __syncthreads();
    {
        #pragma unroll
        for (int f = 0; f < 2; f++)
            #pragma unroll
            for (int nt = 0; nt < 8; nt++) {
                int col = wn * 64 + nt * 8 + 2 * (lane & 3);
                int row = r0 + f * 16;
                float2 bb = *(float2*)(smf + F_B1 + col);
                float* c = C[f * 8 + nt];
                float v0 = fmaxf(c[0] + bb.x, 0.f), v1 = fmaxf(c[1] + bb.y, 0.f);
                float v2 = fmaxf(c[2] + bb.x, 0.f), v3 = fmaxf(c[3] + bb.y, 0.f);
                uint32_t o0 = (uint32_t)row * AROW + (uint32_t)col * 2u;
                sts32(aP + o0, pack_h2(v0, v1));
                sts32(aP + o0 + 8 * AROW, pack_h2(v2, v3));
            }
    }

    // ---------------- GEMM2: h2 = relu(h1 @ w2 + b2), N=256, K=256 ----------------
    gemm_run<8>(C, 4, aP, bB, wn, wm, lane, tid, t);
    __syncthreads();
    {
        float sp[4] = {0.f, 0.f, 0.f, 0.f};
        #pragma unroll
        for (int f = 0; f < 2; f++)
            #pragma unroll
            for (int nt = 0; nt < 8; nt++) {
                int col = wn * 64 + nt * 8 + 2 * (lane & 3);
                int row = r0 + f * 16;
                float2 bb = *(float2*)(smf + F_B2 + col);
                float2 ws = *(float2*)(smf + F_WSIG + col);
                float* c = C[f * 8 + nt];
                float v0 = fmaxf(c[0] + bb.x, 0.f), v1 = fmaxf(c[1] + bb.y, 0.f);
                float v2 = fmaxf(c[2] + bb.x, 0.f), v3 = fmaxf(c[3] + bb.y, 0.f);
                sp[f * 2]     = fmaf(v0, ws.x, fmaf(v1, ws.y, sp[f * 2]));
                sp[f * 2 + 1] = fmaf(v2, ws.x, fmaf(v3, ws.y, sp[f * 2 + 1]));
                uint32_t o0 = (uint32_t)row * AROW + (uint32_t)col * 2u;
                sts32(aP + o0, pack_h2(v0, v1));
                sts32(aP + o0 + 8 * AROW, pack_h2(v2, v3));
            }
        #pragma unroll
        for (int q = 0; q < 4; q++) sp[q] = qred(sp[q]);
        if ((lane & 3) == 0) {
            float* P = smf + F_SIGP + wn * 128;
            P[r0]      = sp[0];
            P[r0 + 8]  = sp[1];
            P[r0 + 16] = sp[2];
            P[r0 + 24] = sp[3];
        }
    }

    // ---------------- GEMM3: hd = relu(h2 @ w_dir_top + dc), N=128, K=256 ----------
    gemm_run<4>(C, 4, aP, bB, wn, wm, lane, tid, t);
    __syncthreads();
    {
        int ray = wm >> 1;
        const float* dcp = smf + F_DC + ray * 128;
        float rp[4] = {0,0,0,0}, gp[4] = {0,0,0,0}, bp[4] = {0,0,0,0};
        #pragma unroll
        for (int f = 0; f < 2; f++)
            #pragma unroll
            for (int nt = 0; nt < 4; nt++) {
                int col = wn * 32 + nt * 8 + 2 * (lane & 3);
                float d0 = dcp[col], d1 = dcp[col + 1];
                float* c = C[f * 4 + nt];
                float h0 = fmaxf(c[0] + d0, 0.f), h1 = fmaxf(c[1] + d1, 0.f);
                float h2 = fmaxf(c[2] + d0, 0.f), h3 = fmaxf(c[3] + d1, 0.f);
                const float* w0 = smf + F_WRGB + col * 3;
                const float* w1v = w0 + 3;
                rp[f*2]   = fmaf(h0, w0[0], fmaf(h1, w1v[0], rp[f*2]));
                gp[f*2]   = fmaf(h0, w0[1], fmaf(h1, w1v[1], gp[f*2]));
                bp[f*2]   = fmaf(h0, w0[2], fmaf(h1, w1v[2], bp[f*2]));
                rp[f*2+1] = fmaf(h2, w0[0], fmaf(h3, w1v[0], rp[f*2+1]));
                gp[f*2+1] = fmaf(h2, w0[1], fmaf(h3, w1v[1], gp[f*2+1]));
                bp[f*2+1] = fmaf(h2, w0[2], fmaf(h3, w1v[2], bp[f*2+1]));
            }
        #pragma unroll
        for (int q = 0; q < 4; q++) { rp[q] = qred(rp[q]); gp[q] = qred(gp[q]); bp[q] = qred(bp[q]); }
        if ((lane & 3) == 0) {
            float* P = smf + F_RGBP + wn * 384;
            #pragma unroll
            for (int q = 0; q < 4; q++) {
                int row = r0 + q * 8;
                P[row * 3 + 0] = rp[q]; P[row * 3 + 1] = gp[q]; P[row * 3 + 2] = bp[q];
            }
        }
    }
    __syncthreads();

    if (tid < 128) {
        int row = tid, rr = row >> 6, s = row & 63;
        float sg = smf[F_SIGP + row] + smf[F_SIGP + 128 + row]
                 + smf[F_SIGP + 256 + row] + smf[F_SIGP + 384 + row] + bsigg[0];
        if (s == 63) sg = g_sig_last[ray0 + rr];
        float nrm = smf[F_RAY + rr * 12 + 9];
        smf[F_SIGP + row] = 1.0f - expf(-fmaxf(sg, 0.f) * g_dists[s] * nrm);
        #pragma unroll
        for (int c = 0; c < 3; c++) {
            float v = smf[F_RGBP + row * 3 + c] + smf[F_RGBP + 384 + row * 3 + c]
                    + smf[F_RGBP + 768 + row * 3 + c] + smf[F_RGBP + 1152 + row * 3 + c]
                    + brgbg[c];
            smf[F_RGB + row * 3 + c] = 1.0f / (1.0f + expf(-v));
        }
    }
    __syncthreads();

    if (tid < 2) {
        int ray = ray0 + tid;
        float T = 1.0f, r = 0.0f, g = 0.0f, b = 0.0f;
        #pragma unroll 1
        for (int s = 0; s < NSAMP; s++) {
            int m = tid * 64 + s;
            float a = smf[F_SIGP + m];
            float w = a * T;
            r = fmaf(w, smf[F_RGB + m * 3 + 0], r);
            g = fmaf(w, smf[F_RGB + m * 3 + 1], g);
            b = fmaf(w, smf[F_RGB + m * 3 + 2], b);
            T *= (1.0f - a);
        }
        out[ray * 3 + 0] = r;
        out[ray * 3 + 1] = g;
        out[ray * 3 + 2] = b;
    }
}

extern "C" void kernel_launch(void* const* d_in, const int* in_sizes, int n_in,
                              void* d_out, int out_size) {
    const float* c2w    = (const float*)d_in[0];
    const float* t_rand = (const float*)d_in[1];
    const float* w1     = (const float*)d_in[2];
    const float* b1     = (const float*)d_in[3];
    const float* w2     = (const float*)d_in[4];
    const float* b2     = (const float*)d_in[5];
    const float* w_sig  = (const float*)d_in[6];
    const float* b_sig  = (const float*)d_in[7];
    const float* w_dir  = (const float*)d_in[8];
    const float* b_dir  = (const float*)d_in[9];
    const float* w_rgb  = (const float*)d_in[10];
    const float* b_rgb  = (const float*)d_in[11];
    float* out = (float*)d_out;

    cudaFuncSetAttribute(nerf_v9, cudaFuncAttributeMaxDynamicSharedMemorySize, SMEM_BYTES);

    aux_kernel<<<PREP_BLOCKS + SIG_BLOCKS + 1, 256>>>(c2w, t_rand, w1, b1, w2, b2,
                                                      w_sig, b_sig, w_dir);
    nerf_v9<<<NBLOCKS, 512, SMEM_BYTES>>>(c2w, b1, b2, w_sig, b_sig,
                                          w_dir, b_dir, w_rgb, b_rgb, out);
}

// round 17
// speedup vs baseline: 1.0519x; 1.0111x over previous
#include <cuda_runtime.h>
#include <cuda_fp16.h>
#include <stdint.h>
#include <math.h>

#define NSAMP 64
#define NBLOCKS 5000           // 2 rays per block, M = 128 sample-rows
#define FXc 86.6f
#define NEAR_ 2.0f
#define FAR_ 6.0f
#define DINF 1e10f

// ---------------- global scratch (weights as fp16, [N][K]) ----------------
__device__ float g_z[NSAMP];
__device__ float g_dists[NSAMP];
__device__ float g_sig_last[10000];
__device__ __align__(16) __half g_w1T[256 * 64];
__device__ __align__(16) __half g_w2T[256 * 256];
__device__ __align__(16) __half g_wdT[128 * 256];

// ---------------- smem layout (bytes) ----------------
#define A_OFF     16384u
#define B_OFF     83968u
#define STAGE_B   36864u
#define BROW      144u
#define AROW      528u
#define SMEM_BYTES 194560

// misc float offsets
#define F_RAY   0      // [2][12]
#define F_B1    32
#define F_B2    288
#define F_WSIG  544
#define F_WRGB  800    // 384
#define F_EDIR  1184   // [2][32]
#define F_DC    1248   // [2][128]
#define F_SIGP  1504   // [4][128]
#define F_RGB   2016   // [128][3]
#define F_RGBP  2400   // [4][384]

// ---------------- asm helpers ----------------
__device__ __forceinline__ uint32_t smem_u32(const void* p) {
    uint32_t a;
    asm("{ .reg .u64 t; cvta.to.shared.u64 t, %1; cvt.u32.u64 %0, t; }" : "=r"(a) : "l"(p));
    return a;
}
__device__ __forceinline__ void sts32(uint32_t a, uint32_t v) {
    asm volatile("st.shared.b32 [%0], %1;" :: "r"(a), "r"(v));
}
__device__ __forceinline__ void ldsm4(uint32_t* r, uint32_t addr) {
    asm volatile("ldmatrix.sync.aligned.m8n8.x4.shared.b16 {%0,%1,%2,%3}, [%4];"
        : "=r"(r[0]), "=r"(r[1]), "=r"(r[2]), "=r"(r[3]) : "r"(addr));
}
__device__ __forceinline__ void mma_f16(float* c, const uint32_t* a, uint32_t b0, uint32_t b1) {
    asm volatile(
        "mma.sync.aligned.m16n8k16.row.col.f32.f16.f16.f32 "
        "{%0,%1,%2,%3}, {%4,%5,%6,%7}, {%8,%9}, {%0,%1,%2,%3};"
        : "+f"(c[0]), "+f"(c[1]), "+f"(c[2]), "+f"(c[3])
        : "r"(a[0]), "r"(a[1]), "r"(a[2]), "r"(a[3]), "r"(b0), "r"(b1));
}
__device__ __forceinline__ void cpa16(uint32_t d, const void* s) {
    asm volatile("cp.async.ca.shared.global [%0], [%1], 16;" :: "r"(d), "l"(s));
}
#define CP_COMMIT() asm volatile("cp.async.commit_group;" ::: "memory")
#define CP_WAIT1()  asm volatile("cp.async.wait_group 1;" ::: "memory")

__device__ __forceinline__ uint32_t pack_h2(float a, float b) {
    __half2 h = __floats2half2_rn(a, b);
    return *reinterpret_cast<uint32_t*>(&h);
}
__device__ __forceinline__ float qred(float v) {
    v += __shfl_xor_sync(0xffffffffu, v, 1);
    v += __shfl_xor_sync(0xffffffffu, v, 2);
    return v;
}

// schedule: 9 items = G1 x1, G2 x4, G3 x4 (K=64 chunks)
__device__ __forceinline__ void fill_item(int t, uint32_t bB, int tid) {
    if (t >= 9) return;
    const __half* src; int nrows, kst, kb;
    if (t == 0)      { src = g_w1T; nrows = 256; kst = 64;  kb = 0; }
    else if (t < 5)  { src = g_w2T; nrows = 256; kst = 256; kb = (t - 1) * 64; }
    else             { src = g_wdT; nrows = 128; kst = 256; kb = (t - 5) * 64; }
    uint32_t dst = bB + (uint32_t)(t % 3) * STAGE_B;
    for (int i = tid; i < nrows * 8; i += 512) {
        int n = i >> 3, seg = i & 7;
        cpa16(dst + (uint32_t)n * BROW + (uint32_t)seg * 16u,
              src + n * kst + kb + seg * 8);
    }
}

// GEMM: 4 M-warp-groups x 32 rows; 4 N-warp-groups. K=64/chunk, 3-stage ring,
// one barrier per chunk; next-next chunk's cp.async issued AFTER compute.
template<int NT>
__device__ __forceinline__ void gemm_run(float (*C)[4], int nchunks,
                                         uint32_t aP, uint32_t bB,
                                         int wn, int wm, int lane, int tid, int& t) {
    const uint32_t aBase = aP + (uint32_t)(wm * 32 + (lane & 15)) * AROW
                         + ((uint32_t)(lane >> 4) << 4);
    const uint32_t bOff = (uint32_t)(wn * (NT * 8) + (lane & 7) + ((lane >> 4) << 3)) * BROW
                        + (((uint32_t)(lane >> 3) & 1u) << 4);
    #pragma unroll
    for (int i = 0; i < 2 * NT; i++) { C[i][0] = 0.f; C[i][1] = 0.f; C[i][2] = 0.f; C[i][3] = 0.f; }
    #pragma unroll 1
    for (int ch = 0; ch < nchunks; ch++) {
        CP_WAIT1();
        __syncthreads();
        uint32_t bs = bB + (uint32_t)(t % 3) * STAGE_B + bOff;
        #pragma unroll
        for (int k16 = 0; k16 < 4; k16++) {
            uint32_t kb = (uint32_t)(ch * 128 + k16 * 32);
            uint32_t a0[4], a1[4];
            ldsm4(a0, aBase + kb);
            ldsm4(a1, aBase + 16u * AROW + kb);
            uint32_t b[NT / 2][4];
            #pragma unroll
            for (int p = 0; p < NT / 2; p++)
                ldsm4(b[p], bs + (uint32_t)p * 16u * BROW + (uint32_t)(k16 * 32));
            #pragma unroll
            for (int p = 0; p < NT / 2; p++) {
                mma_f16(C[2 * p],          a0, b[p][0], b[p][1]);
                mma_f16(C[2 * p + 1],      a0, b[p][2], b[p][3]);
                mma_f16(C[NT + 2 * p],     a1, b[p][0], b[p][1]);
                mma_f16(C[NT + 2 * p + 1], a1, b[p][2], b[p][3]);
            }
        }
        fill_item(t + 2, bB, tid);
        CP_COMMIT();
        t++;
    }
}

// ---------------- fused aux kernel ----------------
#define PREP_BLOCKS 448
#define SIG_BLOCKS  1250
__global__ void __launch_bounds__(256) aux_kernel(
    const float* __restrict__ c2w, const float* __restrict__ t_rand,
    const float* __restrict__ w1g, const float* __restrict__ b1g,
    const float* __restrict__ w2g, const float* __restrict__ b2g,
    const float* __restrict__ wsigg, const float* __restrict__ bsigg,
    const float* __restrict__ wdg)
{
    __shared__ float enc[8][64];
    __shared__ float h1s[8][260];
    __shared__ float red[8][8];
    const int bid = blockIdx.x, tid = threadIdx.x;

    if (bid < PREP_BLOCKS) {
        int e = bid * 256 + tid;
        if (e < 16384) {
            int n = e & 255, k = e >> 8;
            g_w1T[n * 64 + k] = __float2half((k < 63) ? w1g[e] : 0.0f);
        } else if (e < 16384 + 65536) {
            int u = e - 16384;
            int n = u & 255, k = u >> 8;
            g_w2T[n * 256 + k] = __float2half(w2g[u]);
        } else {
            int u = e - 16384 - 65536;
            int n = u & 127, k = u >> 7;
            g_wdT[n * 256 + k] = __float2half(wdg[u]);
        }
        return;
    }
    if (bid == PREP_BLOCKS + SIG_BLOCKS) {
        if (tid < NSAMP) {
            int i = tid;
            float t   = (float)i / 63.0f;
            float z0  = NEAR_ * (1.0f - t) + FAR_ * t;
            float tn  = (float)(i + 1) / 63.0f;
            float z0n = NEAR_ * (1.0f - tn) + FAR_ * tn;
            float tp  = (float)(i - 1) / 63.0f;
            float z0p = NEAR_ * (1.0f - tp) + FAR_ * tp;
            float upper = (i < NSAMP - 1) ? 0.5f * (z0 + z0n) : z0;
            float lower = (i > 0) ? 0.5f * (z0p + z0) : z0;
            float z = lower + (upper - lower) * t_rand[i];
            enc[0][i] = z;
            g_z[i] = z;
        }
        __syncthreads();
        if (tid < NSAMP)
            g_dists[tid] = (tid < NSAMP - 1) ? (enc[0][tid + 1] - enc[0][tid]) : DINF;
        return;
    }

    const int sb = bid - PREP_BLOCKS;
    int r = tid >> 5, sub = tid & 31;
    {
        int ray = sb * 8 + r;
        int cx = ray % 100, rw = ray / 100;
        float dx = ((float)cx - 50.0f) / FXc;
        float dy = -(((float)rw - 50.0f) / FXc);
        float d0 = dx * c2w[0] + dy * c2w[1] - c2w[2];
        float d1 = dx * c2w[4] + dy * c2w[5] - c2w[6];
        float d2 = dx * c2w[8] + dy * c2w[9] - c2w[10];
        float z062 = NEAR_ * (1.0f - 62.0f / 63.0f) + FAR_ * (62.0f / 63.0f);
        float lower = 0.5f * (z062 + FAR_);
        float z = lower + (FAR_ - lower) * t_rand[63];
        float pt[3];
        pt[0] = fmaf(d0, z, c2w[3]);
        pt[1] = fmaf(d1, z, c2w[7]);
        pt[2] = fmaf(d2, z, c2w[11]);
        #pragma unroll
        for (int q = 0; q < 2; q++) {
            int dd = sub * 2 + q;
            float val = 0.f;
            if (dd < 3) val = pt[dd];
            else if (dd < 63) {
                int u = dd - 3, l = u / 6, r6 = u % 6, cc = r6 % 3;
                float x = pt[cc] * (float)(1 << l);
                val = (r6 < 3) ? sinf(x) : cosf(x);
            }
            enc[r][dd] = val;
        }
    }
    __syncthreads();
    float acc[8];
    {
        float b = b1g[tid];
        #pragma unroll
        for (int i = 0; i < 8; i++) acc[i] = b;
        int k = 0;
        #pragma unroll 1
        for (; k + 3 < 63; k += 4) {
            float wa = w1g[k * 256 + tid];
            float wb = w1g[(k + 1) * 256 + tid];
            float wc = w1g[(k + 2) * 256 + tid];
            float wdv = w1g[(k + 3) * 256 + tid];
            #pragma unroll
            for (int i = 0; i < 8; i++)
                acc[i] = fmaf(enc[i][k], wa,
                         fmaf(enc[i][k + 1], wb,
                         fmaf(enc[i][k + 2], wc,
                         fmaf(enc[i][k + 3], wdv, acc[i]))));
        }
        #pragma unroll
        for (; k < 63; k++) {
            float w = w1g[k * 256 + tid];
            #pragma unroll
            for (int i = 0; i < 8; i++) acc[i] = fmaf(enc[i][k], w, acc[i]);
        }
        #pragma unroll
        for (int i = 0; i < 8; i++) h1s[i][tid] = fmaxf(acc[i], 0.f);
    }
    __syncthreads();
    {
        float b = b2g[tid];
        #pragma unroll
        for (int i = 0; i < 8; i++) acc[i] = b;
        #pragma unroll 1
        for (int k = 0; k < 256; k += 4) {
            float wa = w2g[k * 256 + tid];
            float wb = w2g[(k + 1) * 256 + tid];
            float wc = w2g[(k + 2) * 256 + tid];
            float wdv = w2g[(k + 3) * 256 + tid];
            #pragma unroll
            for (int i = 0; i < 8; i++)
                acc[i] = fmaf(h1s[i][k], wa,
                         fmaf(h1s[i][k + 1], wb,
                         fmaf(h1s[i][k + 2], wc,
                         fmaf(h1s[i][k + 3], wdv, acc[i]))));
        }
    }
    {
        float ws = wsigg[tid];
        #pragma unroll
        for (int i = 0; i < 8; i++) {
            float v = fmaxf(acc[i], 0.f) * ws;
            v += __shfl_xor_sync(0xffffffffu, v, 16);
            v += __shfl_xor_sync(0xffffffffu, v, 8);
            v += __shfl_xor_sync(0xffffffffu, v, 4);
            v += __shfl_xor_sync(0xffffffffu, v, 2);
            v += __shfl_xor_sync(0xffffffffu, v, 1);
            if ((tid & 31) == 0) red[i][tid >> 5] = v;
        }
        __syncthreads();
        if (tid < 8) {
            float s = bsigg[0];
            #pragma unroll
            for (int w = 0; w < 8; w++) s += red[tid][w];
            g_sig_last[sb * 8 + tid] = s;
        }
    }
}

// ---------------- main fused kernel (512 threads) ----------------
__global__ void __launch_bounds__(512, 1) nerf_v10(
    const float* __restrict__ c2w,
    const float* __restrict__ b1g,  const float* __restrict__ b2g,
    const float* __restrict__ wsigg,const float* __restrict__ bsigg,
    const float* __restrict__ wdirg,const float* __restrict__ bdirg,
    const float* __restrict__ wrgbg,const float* __restrict__ brgbg,
    float* __restrict__ out)
{
    extern __shared__ char smraw[];
    float* smf = (float*)smraw;
    const uint32_t base = smem_u32(smraw);
    const uint32_t aP = base + A_OFF, bB = base + B_OFF;
    const int tid = threadIdx.x, lane = tid & 31, wid = tid >> 5;
    const int wn = wid & 3, wm = wid >> 2;
    const int r0 = wm * 32 + (lane >> 2);
    const int ray0 = blockIdx.x * 2;
    int t = 0;

    fill_item(0, bB, tid); CP_COMMIT();
    fill_item(1, bB, tid); CP_COMMIT();

    if (tid < 256) {
        smf[F_B1 + tid]   = b1g[tid];
        smf[F_B2 + tid]   = b2g[tid];
        smf[F_WSIG + tid] = wsigg[tid];
    }
    if (tid < 384) smf[F_WRGB + tid] = wrgbg[tid];
    if (tid < 2) {
        int ray = ray0 + tid;
        int c = ray % 100, rw = ray / 100;
        float dx = ((float)c - 50.0f) / FXc;
        float dy = -(((float)rw - 50.0f) / FXc);
        float d0 = dx * c2w[0] + dy * c2w[1] - c2w[2];
        float d1 = dx * c2w[4] + dy * c2w[5] - c2w[6];
        float d2 = dx * c2w[8] + dy * c2w[9] - c2w[10];
        float nrm = sqrtf(d0 * d0 + d1 * d1 + d2 * d2);
        float* R = smf + F_RAY + tid * 12;
        R[0] = c2w[3]; R[1] = c2w[7]; R[2] = c2w[11];
        R[3] = d0; R[4] = d1; R[5] = d2;
        R[6] = d0 / nrm; R[7] = d1 / nrm; R[8] = d2 / nrm;
        R[9] = nrm;
    }
    __syncthreads();

    // ---- warp-specialized prologue ----
    // warps 0-3: posenc -> A plane.  warps 8-15: edir -> (named bar) -> dc.
    // warps 4-7: fall through to the first GEMM wait.
    if (tid < 128) {
        int rr = tid >> 6, s = tid & 63;
        float z = g_z[s];
        const float* R = smf + F_RAY + rr * 12;
        float v[64];
        float f0 = fmaf(R[3], z, R[0]);
        float f1 = fmaf(R[4], z, R[1]);
        float f2 = fmaf(R[5], z, R[2]);
        v[0] = f0; v[1] = f1; v[2] = f2;
        #pragma unroll
        for (int l = 0; l < 10; l++) {
            int b = 3 + l * 6;
            v[b]     = __sinf(f0); v[b + 1] = __sinf(f1); v[b + 2] = __sinf(f2);
            v[b + 3] = __cosf(f0); v[b + 4] = __cosf(f1); v[b + 5] = __cosf(f2);
            f0 *= 2.0f; f1 *= 2.0f; f2 *= 2.0f;
        }
        v[63] = 0.0f;
        uint32_t pk[32];
        #pragma unroll
        for (int i = 0; i < 32; i++) pk[i] = pack_h2(v[2 * i], v[2 * i + 1]);
        char* p = smraw + A_OFF + (uint32_t)tid * AROW;
        #pragma unroll
        for (int q = 0; q < 8; q++)
            *(uint4*)(p + q * 16) = ((uint4*)pk)[q];
    } else if (tid >= 256) {
        int u = tid - 256;
        if (u < 54) {
            int rr = u / 27, dd = u - rr * 27;
            const float* vv = smf + F_RAY + rr * 12 + 6;
            float val;
            if (dd < 3) val = vv[dd];
            else {
                int q = dd - 3, l = q / 6, r6 = q % 6, cc = r6 % 3;
                float x = vv[cc] * (float)(1 << l);
                val = (r6 < 3) ? sinf(x) : cosf(x);
            }
            smf[F_EDIR + rr * 32 + dd] = val;
        }
        asm volatile("bar.sync 1, 256;" ::: "memory");
        {
            int j = u & 127, rr = u >> 7;
            float acc = bdirg[j];
            #pragma unroll
            for (int dd = 0; dd < 27; dd++)
                acc = fmaf(smf[F_EDIR + rr * 32 + dd], wdirg[(256 + dd) * 128 + j], acc);
            smf[F_DC + rr * 128 + j] = acc;
        }
    }

    float C[16][4];

    // ---------------- GEMM1: h1 = relu(enc @ w1 + b1), N=256, K=64 ----------------
    gemm_run<8>(C, 1, aP, bB, wn, wm, lane, tid, t);
    __syncthreads();
    {
        #pragma unroll
        for (int f = 0; f < 2; f++)
            #pragma unroll
            for (int nt = 0; nt < 8; nt++) {
                int col = wn * 64 + nt * 8 + 2 * (lane & 3);
                int row = r0 + f * 16;
                float2 bb = *(float2*)(smf + F_B1 + col);
                float* c = C[f * 8 + nt];
                float v0 = fmaxf(c[0] + bb.x, 0.f), v1 = fmaxf(c[1] + bb.y, 0.f);
                float v2 = fmaxf(c[2] + bb.x, 0.f), v3 = fmaxf(c[3] + bb.y, 0.f);
                uint32_t o0 = (uint32_t)row * AROW + (uint32_t)col * 2u;
                sts32(aP + o0, pack_h2(v0, v1));
                sts32(aP + o0 + 8 * AROW, pack_h2(v2, v3));
            }
    }

    // ---------------- GEMM2: h2 = relu(h1 @ w2 + b2), N=256, K=256 ----------------
    gemm_run<8>(C, 4, aP, bB, wn, wm, lane, tid, t);
    __syncthreads();
    {
        float sp[4] = {0.f, 0.f, 0.f, 0.f};
        #pragma unroll
        for (int f = 0; f < 2; f++)
            #pragma unroll
            for (int nt = 0; nt < 8; nt++) {
                int col = wn * 64 + nt * 8 + 2 * (lane & 3);
                int row = r0 + f * 16;
                float2 bb = *(float2*)(smf + F_B2 + col);
                float2 ws = *(float2*)(smf + F_WSIG + col);
                float* c = C[f * 8 + nt];
                float v0 = fmaxf(c[0] + bb.x, 0.f), v1 = fmaxf(c[1] + bb.y, 0.f);
                float v2 = fmaxf(c[2] + bb.x, 0.f), v3 = fmaxf(c[3] + bb.y, 0.f);
                sp[f * 2]     = fmaf(v0, ws.x, fmaf(v1, ws.y, sp[f * 2]));
                sp[f * 2 + 1] = fmaf(v2, ws.x, fmaf(v3, ws.y, sp[f * 2 + 1]));
                uint32_t o0 = (uint32_t)row * AROW + (uint32_t)col * 2u;
                sts32(aP + o0, pack_h2(v0, v1));
                sts32(aP + o0 + 8 * AROW, pack_h2(v2, v3));
            }
        #pragma unroll
        for (int q = 0; q < 4; q++) sp[q] = qred(sp[q]);
        if ((lane & 3) == 0) {
            float* P = smf + F_SIGP + wn * 128;
            P[r0]      = sp[0];
            P[r0 + 8]  = sp[1];
            P[r0 + 16] = sp[2];
            P[r0 + 24] = sp[3];
        }
    }

    // ---------------- GEMM3: hd = relu(h2 @ w_dir_top + dc), N=128, K=256 ----------
    gemm_run<4>(C, 4, aP, bB, wn, wm, lane, tid, t);
    __syncthreads();
    {
        int ray = wm >> 1;
        const float* dcp = smf + F_DC + ray * 128;
        float rp[4] = {0,0,0,0}, gp[4] = {0,0,0,0}, bp[4] = {0,0,0,0};
        #pragma unroll
        for (int f = 0; f < 2; f++)
            #pragma unroll
            for (int nt = 0; nt < 4; nt++) {
                int col = wn * 32 + nt * 8 + 2 * (lane & 3);
                float d0 = dcp[col], d1 = dcp[col + 1];
                float* c = C[f * 4 + nt];
                float h0 = fmaxf(c[0] + d0, 0.f), h1 = fmaxf(c[1] + d1, 0.f);
                float h2 = fmaxf(c[2] + d0, 0.f), h3 = fmaxf(c[3] + d1, 0.f);
                const float* w0 = smf + F_WRGB + col * 3;
                const float* w1v = w0 + 3;
                rp[f*2]   = fmaf(h0, w0[0], fmaf(h1, w1v[0], rp[f*2]));
                gp[f*2]   = fmaf(h0, w0[1], fmaf(h1, w1v[1], gp[f*2]));
                bp[f*2]   = fmaf(h0, w0[2], fmaf(h1, w1v[2], bp[f*2]));
                rp[f*2+1] = fmaf(h2, w0[0], fmaf(h3, w1v[0], rp[f*2+1]));
                gp[f*2+1] = fmaf(h2, w0[1], fmaf(h3, w1v[1], gp[f*2+1]));
                bp[f*2+1] = fmaf(h2, w0[2], fmaf(h3, w1v[2], bp[f*2+1]));
            }
        #pragma unroll
        for (int q = 0; q < 4; q++) { rp[q] = qred(rp[q]); gp[q] = qred(gp[q]); bp[q] = qred(bp[q]); }
        if ((lane & 3) == 0) {
            float* P = smf + F_RGBP + wn * 384;
            #pragma unroll
            for (int q = 0; q < 4; q++) {
                int row = r0 + q * 8;
                P[row * 3 + 0] = rp[q]; P[row * 3 + 1] = gp[q]; P[row * 3 + 2] = bp[q];
            }
        }
    }
    __syncthreads();

    if (tid < 128) {
        int row = tid, rr = row >> 6, s = row & 63;
        float sg = smf[F_SIGP + row] + smf[F_SIGP + 128 + row]
                 + smf[F_SIGP + 256 + row] + smf[F_SIGP + 384 + row] + bsigg[0];
        if (s == 63) sg = g_sig_last[ray0 + rr];
        float nrm = smf[F_RAY + rr * 12 + 9];
        smf[F_SIGP + row] = 1.0f - expf(-fmaxf(sg, 0.f) * g_dists[s] * nrm);
        #pragma unroll
        for (int c = 0; c < 3; c++) {
            float v = smf[F_RGBP + row * 3 + c] + smf[F_RGBP + 384 + row * 3 + c]
                    + smf[F_RGBP + 768 + row * 3 + c] + smf[F_RGBP + 1152 + row * 3 + c]
                    + brgbg[c];
            smf[F_RGB + row * 3 + c] = 1.0f / (1.0f + expf(-v));
        }
    }
    __syncthreads();

    if (tid < 2) {
        int ray = ray0 + tid;
        float T = 1.0f, r = 0.0f, g = 0.0f, b = 0.0f;
        #pragma unroll 1
        for (int s = 0; s < NSAMP; s++) {
            int m = tid * 64 + s;
            float a = smf[F_SIGP + m];
            float w = a * T;
            r = fmaf(w, smf[F_RGB + m * 3 + 0], r);
            g = fmaf(w, smf[F_RGB + m * 3 + 1], g);
            b = fmaf(w, smf[F_RGB + m * 3 + 2], b);
            T *= (1.0f - a);
        }
        out[ray * 3 + 0] = r;
        out[ray * 3 + 1] = g;
        out[ray * 3 + 2] = b;
    }
}

extern "C" void kernel_launch(void* const* d_in, const int* in_sizes, int n_in,
                              void* d_out, int out_size) {
    const float* c2w    = (const float*)d_in[0];
    const float* t_rand = (const float*)d_in[1];
    const float* w1     = (const float*)d_in[2];
    const float* b1     = (const float*)d_in[3];
    const float* w2     = (const float*)d_in[4];
    const float* b2     = (const float*)d_in[5];
    const float* w_sig  = (const float*)d_in[6];
    const float* b_sig  = (const float*)d_in[7];
    const float* w_dir  = (const float*)d_in[8];
    const float* b_dir  = (const float*)d_in[9];
    const float* w_rgb  = (const float*)d_in[10];
    const float* b_rgb  = (const float*)d_in[11];
    float* out = (float*)d_out;

    cudaFuncSetAttribute(nerf_v10, cudaFuncAttributeMaxDynamicSharedMemorySize, SMEM_BYTES);

    aux_kernel<<<PREP_BLOCKS + SIG_BLOCKS + 1, 256>>>(c2w, t_rand, w1, b1, w2, b2,
                                                      w_sig, b_sig, w_dir);
    nerf_v10<<<NBLOCKS, 512, SMEM_BYTES>>>(c2w, b1, b2, w_sig, b_sig,
                                           w_dir, b_dir, w_rgb, b_rgb, out);
}